// round 3
// baseline (speedup 1.0000x reference)
#include <cuda_runtime.h>

// Precomputed conj-weight unit phasors (cos w, sin w); conj applied at use site.
__device__ __align__(16) float2 g_w1c[16];     // [o][k], k = di*2+dj (pairs -> float4)
// conv2 packed for float4 dj-pair loads: f4 = ((c*4+di)*2 + dj/2)*8 + o
__device__ __align__(16) float2 g_w2c[512];
__device__ __align__(16) float2 g_ffwc[2880];  // [n][j], j contiguous per output n

__global__ void precompute_weights(const float* __restrict__ w1,
                                   const float* __restrict__ w2,
                                   const float* __restrict__ ffw) {
    int t = threadIdx.x;
    if (t < 16) {
        float s, c; sincosf(w1[t], &s, &c);
        g_w1c[t] = make_float2(c, s);
    }
    for (int i = t; i < 512; i += blockDim.x) {
        int o = i >> 6, r = i & 63;                       // [o][c][di][dj]
        int cc = r >> 4, di = (r >> 2) & 3, dj = r & 3;
        float s, c; sincosf(w2[i], &s, &c);
        int f4 = ((cc * 4 + di) * 2 + (dj >> 1)) * 8 + o;
        g_w2c[f4 * 2 + (dj & 1)] = make_float2(c, s);
    }
    for (int i = t; i < 2880; i += blockDim.x) {
        int j = i / 10, n = i % 10;                       // [j][n] -> [n][j]
        float s, c; sincosf(ffw[i], &s, &c);
        g_ffwc[n * 288 + j] = make_float2(c, s);
    }
}

// complex dot accumulate: S += e * conj(w), on packed pairs (x,y),(z,w)
#define CDOT(SX, SY, E, W)                                        \
    SX += (E).x * (W).x + (E).y * (W).y + (E).z * (W).z + (E).w * (W).w; \
    SY += (E).y * (W).x - (E).x * (W).y + (E).w * (W).z - (E).z * (W).w;

__global__ __launch_bounds__(320, 5)
void ringnn_kernel(const float* __restrict__ x, float* __restrict__ out) {
    __shared__ float4 s_z[2][392];                 // pixel phasor pairs
    __shared__ __align__(16) float2 s_e1[2][784];  // conv1 out [c][i][j]
    __shared__ __align__(16) float2 s_f[2][288];   // conv2 out [(pos)*8+o]
    __shared__ float4 s_w1[8];
    __shared__ float4 s_w2[256];

    const int tid = threadIdx.x;
    const int b = blockIdx.x;            // handles images 2b, 2b+1

    if (tid < 8)   s_w1[tid] = ((const float4*)g_w1c)[tid];
    if (tid < 256) s_w2[tid] = ((const float4*)g_w2c)[tid];

    // ---- Phase 1: pixel phasors for 2 images ----
    const float4* x4 = (const float4*)x + (size_t)b * 392;
    for (int i = tid; i < 392; i += 320) {
        int img = i / 196, q = i % 196;
        float4 xv = __ldg(x4 + img * 196 + q);
        float s0, c0, s1, c1, s2, c2, s3, c3;
        __sincosf(xv.x, &s0, &c0);
        __sincosf(xv.y, &s1, &c1);
        __sincosf(xv.z, &s2, &c2);
        __sincosf(xv.w, &s3, &c3);
        s_z[img][2 * q]     = make_float4(c0, s0, c1, s1);
        s_z[img][2 * q + 1] = make_float4(c2, s2, c3, s3);
    }
    __syncthreads();

    // ---- Phase 2: ring conv1, c-blocked (thread = patch, all 4 out-ch) ----
    for (int t = tid; t < 392; t += 320) {
        int img = t / 196, p = t % 196;
        int i = p / 14, j = p % 14;
        float4 za = s_z[img][i * 28 + j];
        float4 zb = s_z[img][i * 28 + 14 + j];
        #pragma unroll
        for (int c = 0; c < 4; c++) {
            float4 wa = s_w1[c * 2], wb = s_w1[c * 2 + 1];
            float Sx = 0.f, Sy = 0.f;
            CDOT(Sx, Sy, za, wa);
            CDOT(Sx, Sy, zb, wb);
            float inv = rsqrtf(fmaxf(Sx * Sx + Sy * Sy, 1e-36f));
            s_e1[img][c * 196 + p] = make_float2(Sx * inv, Sy * inv);
        }
    }
    __syncthreads();

    // ---- Phase 3: ring conv2, 2x2 output-position tile per thread ----
    // thread (img, up, vp, o): outputs (u,v) = (2up+a, 2vp+b), a,b in {0,1}
    if (tid < 144) {
        int o = tid & 7;
        int t9 = (tid >> 3) % 9;
        int img = tid / 72;
        int up = t9 / 3, vp = t9 % 3;
        const float4* e4 = (const float4*)s_e1[img];
        float Sx00 = 0.f, Sy00 = 0.f, Sx01 = 0.f, Sy01 = 0.f;
        float Sx10 = 0.f, Sy10 = 0.f, Sx11 = 0.f, Sy11 = 0.f;
        #pragma unroll
        for (int c = 0; c < 4; c++) {
            #pragma unroll
            for (int di = 0; di < 4; di++) {
                int wb4 = ((c * 4 + di) * 2) * 8 + o;
                float4 W0 = s_w2[wb4];
                float4 W1 = s_w2[wb4 + 8];
                int r0 = 4 * up + di;                 // input row for a=0
                int eb0 = c * 98 + r0 * 7 + 2 * vp;
                float4 A0 = e4[eb0], A1 = e4[eb0 + 1], A2 = e4[eb0 + 2];
                CDOT(Sx00, Sy00, A0, W0); CDOT(Sx00, Sy00, A1, W1);
                CDOT(Sx01, Sy01, A1, W0); CDOT(Sx01, Sy01, A2, W1);
                int eb1 = eb0 + 14;                   // row r0+2 for a=1
                float4 B0 = e4[eb1], B1 = e4[eb1 + 1], B2 = e4[eb1 + 2];
                CDOT(Sx10, Sy10, B0, W0); CDOT(Sx10, Sy10, B1, W1);
                CDOT(Sx11, Sy11, B1, W0); CDOT(Sx11, Sy11, B2, W1);
            }
        }
        int u0 = 2 * up, v0 = 2 * vp;
        float inv;
        inv = rsqrtf(fmaxf(Sx00 * Sx00 + Sy00 * Sy00, 1e-36f));
        s_f[img][(u0 * 6 + v0) * 8 + o]           = make_float2(Sx00 * inv, Sy00 * inv);
        inv = rsqrtf(fmaxf(Sx01 * Sx01 + Sy01 * Sy01, 1e-36f));
        s_f[img][(u0 * 6 + v0 + 1) * 8 + o]       = make_float2(Sx01 * inv, Sy01 * inv);
        inv = rsqrtf(fmaxf(Sx10 * Sx10 + Sy10 * Sy10, 1e-36f));
        s_f[img][((u0 + 1) * 6 + v0) * 8 + o]     = make_float2(Sx10 * inv, Sy10 * inv);
        inv = rsqrtf(fmaxf(Sx11 * Sx11 + Sy11 * Sy11, 1e-36f));
        s_f[img][((u0 + 1) * 6 + v0 + 1) * 8 + o] = make_float2(Sx11 * inv, Sy11 * inv);
    }
    __syncthreads();

    // ---- Phase 4: ring FF. 16-lane group per (img, n); weights from L1 ----
    int g = tid >> 4, l = tid & 15;
    int img = g / 10, n = g % 10;
    const float4* f4v = (const float4*)s_f[img];
    const float4* fw4 = (const float4*)g_ffwc + n * 144;
    float Sx = 0.f, Sy = 0.f;
    #pragma unroll
    for (int pi = l; pi < 144; pi += 16) {
        float4 f = f4v[pi];
        float4 w = __ldg(fw4 + pi);
        CDOT(Sx, Sy, f, w);
    }
    #pragma unroll
    for (int off = 8; off; off >>= 1) {
        Sx += __shfl_xor_sync(0xffffffff, Sx, off, 16);
        Sy += __shfl_xor_sync(0xffffffff, Sy, off, 16);
    }
    if (l == 0) {
        float inv = rsqrtf(fmaxf(Sx * Sx + Sy * Sy, 1e-36f));
        out[(b * 2 + img) * 10 + n] = Sy * inv;     // sin(atan2(Sy,Sx))
    }
}

extern "C" void kernel_launch(void* const* d_in, const int* in_sizes, int n_in,
                              void* d_out, int out_size) {
    const float* x   = (const float*)d_in[0];   // [B,1,28,28]
    const float* w1  = (const float*)d_in[1];   // [4,1,2,2]
    const float* w2  = (const float*)d_in[2];   // [8,4,4,4]
    const float* ffw = (const float*)d_in[3];   // [288,10]
    float* out = (float*)d_out;                 // [B,10]
    int Bn = in_sizes[0] / 784;

    precompute_weights<<<1, 512>>>(w1, w2, ffw);
    ringnn_kernel<<<Bn / 2, 320>>>(x, out);
}

// round 4
// speedup vs baseline: 1.5706x; 1.5706x over previous
#include <cuda_runtime.h>

// Precomputed conj-weight unit phasors (cos w, sin w); conj applied at use site.
__device__ __align__(16) float2 g_w1c[16];     // [o][k], k = di*2+dj (pairs -> float4)
// conv2 packed for float4 dj-pair loads: f4 = ((c*4+di)*2 + dj/2)*8 + o
__device__ __align__(16) float2 g_w2c[512];
__device__ __align__(16) float2 g_ffwc[2880];  // [n][j], j contiguous per output n

__global__ void precompute_weights(const float* __restrict__ w1,
                                   const float* __restrict__ w2,
                                   const float* __restrict__ ffw) {
    int t = threadIdx.x;
    if (t < 16) {
        float s, c; sincosf(w1[t], &s, &c);
        g_w1c[t] = make_float2(c, s);
    }
    for (int i = t; i < 512; i += blockDim.x) {
        int o = i >> 6, r = i & 63;                       // [o][c][di][dj]
        int cc = r >> 4, di = (r >> 2) & 3, dj = r & 3;
        float s, c; sincosf(w2[i], &s, &c);
        int f4 = ((cc * 4 + di) * 2 + (dj >> 1)) * 8 + o;
        g_w2c[f4 * 2 + (dj & 1)] = make_float2(c, s);
    }
    for (int i = t; i < 2880; i += blockDim.x) {
        int j = i / 10, n = i % 10;                       // [j][n] -> [n][j]
        float s, c; sincosf(ffw[i], &s, &c);
        g_ffwc[n * 288 + j] = make_float2(c, s);
    }
}

// complex dot accumulate: S += e * conj(w), on packed pairs (x,y),(z,w)
#define CDOT(SX, SY, E, W)                                        \
    SX += (E).x * (W).x + (E).y * (W).y + (E).z * (W).z + (E).w * (W).w; \
    SY += (E).y * (W).x - (E).x * (W).y + (E).w * (W).z - (E).z * (W).w;

__global__ __launch_bounds__(320, 4)
void ringnn_kernel(const float* __restrict__ x, float* __restrict__ out) {
    __shared__ float4 s_z[2][392];                 // pixel phasor pairs
    __shared__ __align__(16) float2 s_e1[2][784];  // conv1 out [c][i][j]
    __shared__ __align__(16) float2 s_f[2][288];   // conv2 out [pos*8+o]
    __shared__ float4 s_w1[8];
    __shared__ float4 s_w2[256];

    const int tid = threadIdx.x;
    const int b = blockIdx.x;            // handles images 2b, 2b+1

    if (tid < 8)   s_w1[tid] = ((const float4*)g_w1c)[tid];
    if (tid < 256) s_w2[tid] = ((const float4*)g_w2c)[tid];

    // ---- Phase 1: pixel phasors for 2 images ----
    const float4* x4 = (const float4*)x + (size_t)b * 392;
    for (int i = tid; i < 392; i += 320) {
        int img = i / 196, q = i % 196;
        float4 xv = __ldg(x4 + img * 196 + q);
        float s0, c0, s1, c1, s2, c2, s3, c3;
        __sincosf(xv.x, &s0, &c0);
        __sincosf(xv.y, &s1, &c1);
        __sincosf(xv.z, &s2, &c2);
        __sincosf(xv.w, &s3, &c3);
        s_z[img][2 * q]     = make_float4(c0, s0, c1, s1);
        s_z[img][2 * q + 1] = make_float4(c2, s2, c3, s3);
    }
    __syncthreads();

    // ---- Phase 2: ring conv1, c-blocked (thread = patch, all 4 out-ch) ----
    for (int t = tid; t < 392; t += 320) {
        int img = t / 196, p = t % 196;
        int i = p / 14, j = p % 14;
        float4 za = s_z[img][i * 28 + j];
        float4 zb = s_z[img][i * 28 + 14 + j];
        #pragma unroll
        for (int c = 0; c < 4; c++) {
            float4 wa = s_w1[c * 2], wb = s_w1[c * 2 + 1];
            float Sx = 0.f, Sy = 0.f;
            CDOT(Sx, Sy, za, wa);
            CDOT(Sx, Sy, zb, wb);
            float inv = rsqrtf(fmaxf(Sx * Sx + Sy * Sy, 1e-36f));
            s_e1[img][c * 196 + p] = make_float2(Sx * inv, Sy * inv);
        }
    }
    __syncthreads();

    // ---- Phase 3: ring conv2, 1x2 output tile (v-pair) per thread ----
    // thread (img, u, vp, o): outputs (u, 2vp) and (u, 2vp+1)
    if (tid < 288) {
        int img = tid / 144, r = tid % 144;
        int o = r & 7;
        int q = r >> 3;                  // 0..17
        int u = q / 3, vp = q % 3;
        const float4* e4 = (const float4*)s_e1[img];
        float Sx0 = 0.f, Sy0 = 0.f, Sx1 = 0.f, Sy1 = 0.f;
        #pragma unroll
        for (int c = 0; c < 4; c++) {
            #pragma unroll
            for (int di = 0; di < 4; di++) {
                int wb4 = ((c * 4 + di) * 2) * 8 + o;
                float4 W0 = s_w2[wb4];
                float4 W1 = s_w2[wb4 + 8];
                int eb = c * 98 + (2 * u + di) * 7 + 2 * vp;
                float4 A0 = e4[eb], A1 = e4[eb + 1], A2 = e4[eb + 2];
                CDOT(Sx0, Sy0, A0, W0); CDOT(Sx0, Sy0, A1, W1);
                CDOT(Sx1, Sy1, A1, W0); CDOT(Sx1, Sy1, A2, W1);
            }
        }
        float inv;
        int base = (u * 6 + 2 * vp) * 8 + o;
        inv = rsqrtf(fmaxf(Sx0 * Sx0 + Sy0 * Sy0, 1e-36f));
        s_f[img][base]     = make_float2(Sx0 * inv, Sy0 * inv);
        inv = rsqrtf(fmaxf(Sx1 * Sx1 + Sy1 * Sy1, 1e-36f));
        s_f[img][base + 8] = make_float2(Sx1 * inv, Sy1 * inv);
    }
    __syncthreads();

    // ---- Phase 4: ring FF. 16-lane group per (img, n); weights from L1 ----
    int g = tid >> 4, l = tid & 15;
    int img = g / 10, n = g % 10;
    const float4* f4v = (const float4*)s_f[img];
    const float4* fw4 = (const float4*)g_ffwc + n * 144;
    float Sx = 0.f, Sy = 0.f;
    #pragma unroll
    for (int pi = l; pi < 144; pi += 16) {
        float4 f = f4v[pi];
        float4 w = __ldg(fw4 + pi);
        CDOT(Sx, Sy, f, w);
    }
    #pragma unroll
    for (int off = 8; off; off >>= 1) {
        Sx += __shfl_xor_sync(0xffffffff, Sx, off, 16);
        Sy += __shfl_xor_sync(0xffffffff, Sy, off, 16);
    }
    if (l == 0) {
        float inv = rsqrtf(fmaxf(Sx * Sx + Sy * Sy, 1e-36f));
        out[(b * 2 + img) * 10 + n] = Sy * inv;     // sin(atan2(Sy,Sx))
    }
}

extern "C" void kernel_launch(void* const* d_in, const int* in_sizes, int n_in,
                              void* d_out, int out_size) {
    const float* x   = (const float*)d_in[0];   // [B,1,28,28]
    const float* w1  = (const float*)d_in[1];   // [4,1,2,2]
    const float* w2  = (const float*)d_in[2];   // [8,4,4,4]
    const float* ffw = (const float*)d_in[3];   // [288,10]
    float* out = (float*)d_out;                 // [B,10]
    int Bn = in_sizes[0] / 784;

    precompute_weights<<<1, 512>>>(w1, w2, ffw);
    ringnn_kernel<<<Bn / 2, 320>>>(x, out);
}

// round 5
// speedup vs baseline: 1.6548x; 1.0536x over previous
#include <cuda_runtime.h>

// Precomputed conj-weight unit phasors (cos w, sin w); conj applied at use site.
__device__ __align__(16) float2 g_w1c[16];     // [o][k], k = di*2+dj (pairs -> float4)
// conv2 packed for float4 dj-pair loads: f4 = ((c*4+di)*2 + dj/2)*8 + o
__device__ __align__(16) float2 g_w2c[512];
__device__ __align__(16) float2 g_ffwc[2880];  // [n][j], j contiguous per output n

__global__ void precompute_weights(const float* __restrict__ w1,
                                   const float* __restrict__ w2,
                                   const float* __restrict__ ffw) {
    int t = threadIdx.x;
    if (t < 16) {
        float s, c; sincosf(w1[t], &s, &c);
        g_w1c[t] = make_float2(c, s);
    }
    for (int i = t; i < 512; i += blockDim.x) {
        int o = i >> 6, r = i & 63;                       // [o][c][di][dj]
        int cc = r >> 4, di = (r >> 2) & 3, dj = r & 3;
        float s, c; sincosf(w2[i], &s, &c);
        int f4 = ((cc * 4 + di) * 2 + (dj >> 1)) * 8 + o;
        g_w2c[f4 * 2 + (dj & 1)] = make_float2(c, s);
    }
    for (int i = t; i < 2880; i += blockDim.x) {
        int j = i / 10, n = i % 10;                       // [j][n] -> [n][j]
        float s, c; sincosf(ffw[i], &s, &c);
        g_ffwc[n * 288 + j] = make_float2(c, s);
    }
}

// complex dot accumulate: S += e * conj(w), on packed pairs (x,y),(z,w)
#define CDOT(SX, SY, E, W)                                        \
    SX += (E).x * (W).x + (E).y * (W).y + (E).z * (W).z + (E).w * (W).w; \
    SY += (E).y * (W).x - (E).x * (W).y + (E).w * (W).z - (E).z * (W).w;

__global__ __launch_bounds__(160, 6)
void ringnn_kernel(const float* __restrict__ x, float* __restrict__ out) {
    __shared__ float4 s_z[2][392];                 // pixel phasor pairs
    __shared__ __align__(16) float2 s_e1[2][784];  // conv1 out [c][i][j]
    __shared__ __align__(16) float2 s_f[2][288];   // conv2 out [pos*8+o]
    __shared__ float4 s_w1[8];
    __shared__ float4 s_w2[256];

    const int tid = threadIdx.x;
    const int b = blockIdx.x;            // images 2b, 2b+1

    if (tid < 8) s_w1[tid] = ((const float4*)g_w1c)[tid];
    for (int i = tid; i < 256; i += 160) s_w2[i] = ((const float4*)g_w2c)[i];

    // ---- Phase 1: pixel phasors for 2 images ----
    const float4* x4 = (const float4*)x + (size_t)b * 392;
    for (int i = tid; i < 392; i += 160) {
        int img = i / 196, q = i % 196;
        float4 xv = __ldg(x4 + img * 196 + q);
        float s0, c0, s1, c1, s2, c2, s3, c3;
        __sincosf(xv.x, &s0, &c0);
        __sincosf(xv.y, &s1, &c1);
        __sincosf(xv.z, &s2, &c2);
        __sincosf(xv.w, &s3, &c3);
        s_z[img][2 * q]     = make_float4(c0, s0, c1, s1);
        s_z[img][2 * q + 1] = make_float4(c2, s2, c3, s3);
    }
    __syncthreads();

    // ---- Phase 2: ring conv1, c-blocked (thread = patch, all 4 out-ch) ----
    for (int t = tid; t < 392; t += 160) {
        int img = t / 196, p = t % 196;
        int i = p / 14, j = p % 14;
        float4 za = s_z[img][i * 28 + j];
        float4 zb = s_z[img][i * 28 + 14 + j];
        #pragma unroll
        for (int c = 0; c < 4; c++) {
            float4 wa = s_w1[c * 2], wb = s_w1[c * 2 + 1];
            float Sx = 0.f, Sy = 0.f;
            CDOT(Sx, Sy, za, wa);
            CDOT(Sx, Sy, zb, wb);
            float inv = rsqrtf(fmaxf(Sx * Sx + Sy * Sy, 1e-36f));
            s_e1[img][c * 196 + p] = make_float2(Sx * inv, Sy * inv);
        }
    }
    __syncthreads();

    // ---- Phase 3: ring conv2, 2x2 output tile per thread ----
    // thread (img, up, vp, o): outputs u in {2up,2up+1}, v in {2vp,2vp+1}
    if (tid < 144) {
        int img = tid / 72, r = tid % 72;
        int o = r & 7, t9 = r >> 3;          // t9 in 0..8
        int up = t9 / 3, vp = t9 % 3;
        const float4* e4 = (const float4*)s_e1[img];
        float Sx00 = 0.f, Sy00 = 0.f, Sx01 = 0.f, Sy01 = 0.f;
        float Sx10 = 0.f, Sy10 = 0.f, Sx11 = 0.f, Sy11 = 0.f;
        #pragma unroll
        for (int c = 0; c < 4; c++) {
            // preload this c's 8 weight float4s for out-channel o
            float4 W[4][2];
            #pragma unroll
            for (int di = 0; di < 4; di++) {
                int wb4 = ((c * 4 + di) * 2) * 8 + o;
                W[di][0] = s_w2[wb4];
                W[di][1] = s_w2[wb4 + 8];
            }
            int eb = c * 98 + (4 * up) * 7 + 2 * vp;
            #pragma unroll
            for (int r6 = 0; r6 < 6; r6++) {
                float4 A0 = e4[eb + r6 * 7];
                float4 A1 = e4[eb + r6 * 7 + 1];
                float4 A2 = e4[eb + r6 * 7 + 2];
                if (r6 < 4) {   // u = 2up, di = r6
                    CDOT(Sx00, Sy00, A0, W[r6][0]); CDOT(Sx00, Sy00, A1, W[r6][1]);
                    CDOT(Sx01, Sy01, A1, W[r6][0]); CDOT(Sx01, Sy01, A2, W[r6][1]);
                }
                if (r6 >= 2) {  // u = 2up+1, di = r6-2
                    CDOT(Sx10, Sy10, A0, W[r6 - 2][0]); CDOT(Sx10, Sy10, A1, W[r6 - 2][1]);
                    CDOT(Sx11, Sy11, A1, W[r6 - 2][0]); CDOT(Sx11, Sy11, A2, W[r6 - 2][1]);
                }
            }
        }
        int u0 = 2 * up, v0 = 2 * vp;
        float inv;
        inv = rsqrtf(fmaxf(Sx00 * Sx00 + Sy00 * Sy00, 1e-36f));
        s_f[img][(u0 * 6 + v0) * 8 + o]           = make_float2(Sx00 * inv, Sy00 * inv);
        inv = rsqrtf(fmaxf(Sx01 * Sx01 + Sy01 * Sy01, 1e-36f));
        s_f[img][(u0 * 6 + v0 + 1) * 8 + o]       = make_float2(Sx01 * inv, Sy01 * inv);
        inv = rsqrtf(fmaxf(Sx10 * Sx10 + Sy10 * Sy10, 1e-36f));
        s_f[img][((u0 + 1) * 6 + v0) * 8 + o]     = make_float2(Sx10 * inv, Sy10 * inv);
        inv = rsqrtf(fmaxf(Sx11 * Sx11 + Sy11 * Sy11, 1e-36f));
        s_f[img][((u0 + 1) * 6 + v0 + 1) * 8 + o] = make_float2(Sx11 * inv, Sy11 * inv);
    }
    __syncthreads();

    // ---- Phase 4: ring FF. 8-lane group per (img, n); weights from L1 ----
    int g = tid >> 3, l = tid & 7;       // 20 groups = 2 img x 10 outputs
    int img = g / 10, n = g % 10;
    const float4* f4v = (const float4*)s_f[img];
    const float4* fw4 = (const float4*)g_ffwc + n * 144;
    float Sx = 0.f, Sy = 0.f;
    #pragma unroll
    for (int pi = l; pi < 144; pi += 8) {
        float4 f = f4v[pi];
        float4 w = __ldg(fw4 + pi);
        CDOT(Sx, Sy, f, w);
    }
    #pragma unroll
    for (int off = 4; off; off >>= 1) {
        Sx += __shfl_xor_sync(0xffffffff, Sx, off, 8);
        Sy += __shfl_xor_sync(0xffffffff, Sy, off, 8);
    }
    if (l == 0) {
        float inv = rsqrtf(fmaxf(Sx * Sx + Sy * Sy, 1e-36f));
        out[(b * 2 + img) * 10 + n] = Sy * inv;     // sin(atan2(Sy,Sx))
    }
}

extern "C" void kernel_launch(void* const* d_in, const int* in_sizes, int n_in,
                              void* d_out, int out_size) {
    const float* x   = (const float*)d_in[0];   // [B,1,28,28]
    const float* w1  = (const float*)d_in[1];   // [4,1,2,2]
    const float* w2  = (const float*)d_in[2];   // [8,4,4,4]
    const float* ffw = (const float*)d_in[3];   // [288,10]
    float* out = (float*)d_out;                 // [B,10]
    int Bn = in_sizes[0] / 784;

    precompute_weights<<<1, 512>>>(w1, w2, ffw);
    ringnn_kernel<<<Bn / 2, 160>>>(x, out);
}

// round 6
// speedup vs baseline: 1.7837x; 1.0779x over previous
#include <cuda_runtime.h>

// Precomputed conj-weight unit phasors (cos w, sin w); conj applied at use site.
__device__ __align__(16) float2 g_w1c[16];     // [o][k], k = di*2+dj (pairs -> float4)
// conv2 packed for float4 dj-pair loads: f4 = ((c*4+di)*2 + dj/2)*8 + o
__device__ __align__(16) float2 g_w2c[512];
__device__ __align__(16) float2 g_ffwc[2880];  // [n][j], j contiguous per output n

__global__ void precompute_weights(const float* __restrict__ w1,
                                   const float* __restrict__ w2,
                                   const float* __restrict__ ffw) {
    int t = threadIdx.x;
    if (t < 16) {
        float s, c; sincosf(w1[t], &s, &c);
        g_w1c[t] = make_float2(c, s);
    }
    for (int i = t; i < 512; i += blockDim.x) {
        int o = i >> 6, r = i & 63;                       // [o][c][di][dj]
        int cc = r >> 4, di = (r >> 2) & 3, dj = r & 3;
        float s, c; sincosf(w2[i], &s, &c);
        int f4 = ((cc * 4 + di) * 2 + (dj >> 1)) * 8 + o;
        g_w2c[f4 * 2 + (dj & 1)] = make_float2(c, s);
    }
    for (int i = t; i < 2880; i += blockDim.x) {
        int j = i / 10, n = i % 10;                       // [j][n] -> [n][j]
        float s, c; sincosf(ffw[i], &s, &c);
        g_ffwc[n * 288 + j] = make_float2(c, s);
    }
}

// complex dot accumulate: S += e * conj(w), on packed pairs (x,y),(z,w)
#define CDOT(SX, SY, E, W)                                        \
    SX += (E).x * (W).x + (E).y * (W).y + (E).z * (W).z + (E).w * (W).w; \
    SY += (E).y * (W).x - (E).x * (W).y + (E).w * (W).z - (E).z * (W).w;

__global__ __launch_bounds__(160, 6)
void ringnn_kernel(const float* __restrict__ x, float* __restrict__ out) {
    __shared__ __align__(16) float2 s_e1[2][784];  // conv1 out [c][i][j]
    __shared__ __align__(16) float2 s_f[2][288];   // conv2 out [pos*8+o]
    __shared__ float4 s_w2[256];

    const int tid = threadIdx.x;
    const int b = blockIdx.x;            // images 2b, 2b+1

    for (int i = tid; i < 256; i += 160) s_w2[i] = ((const float4*)g_w2c)[i];

    // ---- Phase 1+2 fused: conv1 patches are non-overlapping (2x2 stride 2),
    //      so load the 4 pixels straight from GMEM, sincos in registers.
    const float* xb = x + (size_t)b * 1568;
    for (int t = tid; t < 392; t += 160) {
        int img = t / 196, p = t % 196;
        int i = p / 14, j = p % 14;
        const float* px = xb + img * 784 + (2 * i) * 28 + 2 * j;
        float2 r0 = __ldg((const float2*)px);
        float2 r1 = __ldg((const float2*)(px + 28));
        float c0, s0, c1, s1, c2, s2, c3, s3;
        __sincosf(r0.x, &s0, &c0);
        __sincosf(r0.y, &s1, &c1);
        __sincosf(r1.x, &s2, &c2);
        __sincosf(r1.y, &s3, &c3);
        float4 za = make_float4(c0, s0, c1, s1);
        float4 zb = make_float4(c2, s2, c3, s3);
        #pragma unroll
        for (int c = 0; c < 4; c++) {
            float4 wa = __ldg((const float4*)g_w1c + c * 2);
            float4 wb = __ldg((const float4*)g_w1c + c * 2 + 1);
            float Sx = 0.f, Sy = 0.f;
            CDOT(Sx, Sy, za, wa);
            CDOT(Sx, Sy, zb, wb);
            float inv = rsqrtf(fmaxf(Sx * Sx + Sy * Sy, 1e-36f));
            s_e1[img][c * 196 + p] = make_float2(Sx * inv, Sy * inv);
        }
    }
    __syncthreads();

    // ---- Phase 3: ring conv2, 2x2 output tile per thread ----
    // thread (img, up, vp, o): outputs u in {2up,2up+1}, v in {2vp,2vp+1}
    if (tid < 144) {
        int img = tid / 72, r = tid % 72;
        int o = r & 7, t9 = r >> 3;          // t9 in 0..8
        int up = t9 / 3, vp = t9 % 3;
        const float4* e4 = (const float4*)s_e1[img];
        float Sx00 = 0.f, Sy00 = 0.f, Sx01 = 0.f, Sy01 = 0.f;
        float Sx10 = 0.f, Sy10 = 0.f, Sx11 = 0.f, Sy11 = 0.f;
        #pragma unroll
        for (int c = 0; c < 4; c++) {
            float4 W[4][2];
            #pragma unroll
            for (int di = 0; di < 4; di++) {
                int wb4 = ((c * 4 + di) * 2) * 8 + o;
                W[di][0] = s_w2[wb4];
                W[di][1] = s_w2[wb4 + 8];
            }
            int eb = c * 98 + (4 * up) * 7 + 2 * vp;
            #pragma unroll
            for (int r6 = 0; r6 < 6; r6++) {
                float4 A0 = e4[eb + r6 * 7];
                float4 A1 = e4[eb + r6 * 7 + 1];
                float4 A2 = e4[eb + r6 * 7 + 2];
                if (r6 < 4) {   // u = 2up, di = r6
                    CDOT(Sx00, Sy00, A0, W[r6][0]); CDOT(Sx00, Sy00, A1, W[r6][1]);
                    CDOT(Sx01, Sy01, A1, W[r6][0]); CDOT(Sx01, Sy01, A2, W[r6][1]);
                }
                if (r6 >= 2) {  // u = 2up+1, di = r6-2
                    CDOT(Sx10, Sy10, A0, W[r6 - 2][0]); CDOT(Sx10, Sy10, A1, W[r6 - 2][1]);
                    CDOT(Sx11, Sy11, A1, W[r6 - 2][0]); CDOT(Sx11, Sy11, A2, W[r6 - 2][1]);
                }
            }
        }
        int u0 = 2 * up, v0 = 2 * vp;
        float inv;
        inv = rsqrtf(fmaxf(Sx00 * Sx00 + Sy00 * Sy00, 1e-36f));
        s_f[img][(u0 * 6 + v0) * 8 + o]           = make_float2(Sx00 * inv, Sy00 * inv);
        inv = rsqrtf(fmaxf(Sx01 * Sx01 + Sy01 * Sy01, 1e-36f));
        s_f[img][(u0 * 6 + v0 + 1) * 8 + o]       = make_float2(Sx01 * inv, Sy01 * inv);
        inv = rsqrtf(fmaxf(Sx10 * Sx10 + Sy10 * Sy10, 1e-36f));
        s_f[img][((u0 + 1) * 6 + v0) * 8 + o]     = make_float2(Sx10 * inv, Sy10 * inv);
        inv = rsqrtf(fmaxf(Sx11 * Sx11 + Sy11 * Sy11, 1e-36f));
        s_f[img][((u0 + 1) * 6 + v0 + 1) * 8 + o] = make_float2(Sx11 * inv, Sy11 * inv);
    }
    __syncthreads();

    // ---- Phase 4: ring FF. 8-lane group per (img, n); weights from L1 ----
    int g = tid >> 3, l = tid & 7;       // 20 groups = 2 img x 10 outputs
    int img = g / 10, n = g % 10;
    const float4* f4v = (const float4*)s_f[img];
    const float4* fw4 = (const float4*)g_ffwc + n * 144;
    float Sx = 0.f, Sy = 0.f;
    #pragma unroll
    for (int pi = l; pi < 144; pi += 8) {
        float4 f = f4v[pi];
        float4 w = __ldg(fw4 + pi);
        CDOT(Sx, Sy, f, w);
    }
    #pragma unroll
    for (int off = 4; off; off >>= 1) {
        Sx += __shfl_xor_sync(0xffffffff, Sx, off, 8);
        Sy += __shfl_xor_sync(0xffffffff, Sy, off, 8);
    }
    if (l == 0) {
        float inv = rsqrtf(fmaxf(Sx * Sx + Sy * Sy, 1e-36f));
        out[(b * 2 + img) * 10 + n] = Sy * inv;     // sin(atan2(Sy,Sx))
    }
}

extern "C" void kernel_launch(void* const* d_in, const int* in_sizes, int n_in,
                              void* d_out, int out_size) {
    const float* x   = (const float*)d_in[0];   // [B,1,28,28]
    const float* w1  = (const float*)d_in[1];   // [4,1,2,2]
    const float* w2  = (const float*)d_in[2];   // [8,4,4,4]
    const float* ffw = (const float*)d_in[3];   // [288,10]
    float* out = (float*)d_out;                 // [B,10]
    int Bn = in_sizes[0] / 784;

    precompute_weights<<<1, 512>>>(w1, w2, ffw);
    ringnn_kernel<<<Bn / 2, 160>>>(x, out);
}